// round 13
// baseline (speedup 1.0000x reference)
#include <cuda_runtime.h>
#include <math.h>

#define DD 256
#define BATCH 4
#define NN 512

typedef unsigned long long u64;

// Scratch: xp = x @ Wx  (B*N, D);  ypb = y @ Wy + b1  (B*N, D)
__device__ float g_xp[BATCH * NN * DD];
__device__ float g_ypb[BATCH * NN * DD];

// ---- f32x2 packed-math primitives ------------------------------------------
#define F2FMA(D_, A_, B_, C_) \
    asm("fma.rn.f32x2 %0, %1, %2, %3;" : "=l"(D_) : "l"(A_), "l"(B_), "l"(C_))
#define F2ADD(D_, A_, B_) \
    asm("add.rn.f32x2 %0, %1, %2;" : "=l"(D_) : "l"(A_), "l"(B_))
#define F2MUL(D_, A_, B_) \
    asm("mul.rn.f32x2 %0, %1, %2;" : "=l"(D_) : "l"(A_), "l"(B_))
#define PK(D_, LO_, HI_) \
    asm("mov.b64 %0, {%1, %2};" : "=l"(D_) : "f"(LO_), "f"(HI_))
#define UNPK(LO_, HI_, S_) \
    asm("mov.b64 {%0, %1}, %2;" : "=f"(LO_), "=f"(HI_) : "l"(S_))

__device__ __forceinline__ float tanh_fast(float v) {
    float r;
    asm("tanh.approx.f32 %0, %1;" : "=f"(r) : "f"(v));
    return r;
}

#define GC0 0.79788456080286536f          // sqrt(2/pi)
#define GC1 0.03567740813636141f          // sqrt(2/pi)*0.044715

// ---------------------------------------------------------------------------
// Per-batch GEMM: for batch b, z=0: g_xp[b] = x[b] @ W1[0:256];
// z=1: g_ypb[b] = y[b] @ W1[256:512] + b1.
// 32(m) x 64(n) tiles, BK=16, 128 threads, 4x4 micro-tile (R9 scalar inner),
// double-buffered smem + register prefetch, 1 sync/chunk.
// grid (4, 16, 2) = 128 blocks -> ~1 block/SM, minimal per-batch latency.
// ---------------------------------------------------------------------------
__global__ __launch_bounds__(128) void gemm_kernel(
    const float* __restrict__ x,
    const float* __restrict__ y,
    const float* __restrict__ W1,
    const float* __restrict__ b1,
    int b)
{
    __shared__ float As[2][16][36];   // [stage][k][m], 32 m + pad
    __shared__ float Bs[2][16][68];   // [stage][k][n], 64 n + pad

    const int sel = blockIdx.z;
    const float* X = (sel ? y : x) + b * NN * DD;
    const float* W = sel ? (W1 + 256 * 256) : W1;
    float* out = (sel ? g_ypb : g_xp) + b * NN * DD;

    const int tx = threadIdx.x;     // 0..15 -> n
    const int ty = threadIdx.y;     // 0..7  -> m
    const int t  = ty * 16 + tx;
    const int m0 = blockIdx.y * 32;
    const int n0 = blockIdx.x * 64;

    // fill roles
    const int fm = t >> 2;          // A row 0..31
    const int fk = (t & 3) * 4;     // A k quad
    const int gk = t >> 3;          // B k row 0..15
    const int gn = (t & 7) * 8;     // B col octet

    float acc[4][4] = {};

    // prologue: chunk 0 -> stage 0
    float4 av  = *(const float4*)&X[(m0 + fm) * 256 + fk];
    float4 bv0 = *(const float4*)&W[gk * 256 + n0 + gn];
    float4 bv1 = *(const float4*)&W[gk * 256 + n0 + gn + 4];
    As[0][fk + 0][fm] = av.x;
    As[0][fk + 1][fm] = av.y;
    As[0][fk + 2][fm] = av.z;
    As[0][fk + 3][fm] = av.w;
    *(float4*)&Bs[0][gk][gn]     = bv0;
    *(float4*)&Bs[0][gk][gn + 4] = bv1;
    __syncthreads();

    for (int kc = 0; kc < 16; ++kc) {
        const int s = kc & 1;
        if (kc < 15) {
            const int k0 = (kc + 1) * 16;
            av  = *(const float4*)&X[(m0 + fm) * 256 + k0 + fk];
            bv0 = *(const float4*)&W[(k0 + gk) * 256 + n0 + gn];
            bv1 = *(const float4*)&W[(k0 + gk) * 256 + n0 + gn + 4];
        }

        #pragma unroll
        for (int kk = 0; kk < 16; ++kk) {
            float4 a = *(const float4*)&As[s][kk][ty * 4];
            float4 bq = *(const float4*)&Bs[s][kk][tx * 4];
            float avr[4] = {a.x, a.y, a.z, a.w};
            float bvr[4] = {bq.x, bq.y, bq.z, bq.w};
            #pragma unroll
            for (int i = 0; i < 4; ++i)
                #pragma unroll
                for (int j = 0; j < 4; ++j)
                    acc[i][j] = fmaf(avr[i], bvr[j], acc[i][j]);
        }

        if (kc < 15) {
            const int s2 = s ^ 1;
            As[s2][fk + 0][fm] = av.x;
            As[s2][fk + 1][fm] = av.y;
            As[s2][fk + 2][fm] = av.z;
            As[s2][fk + 3][fm] = av.w;
            *(float4*)&Bs[s2][gk][gn]     = bv0;
            *(float4*)&Bs[s2][gk][gn + 4] = bv1;
            __syncthreads();
        }
    }

    #pragma unroll
    for (int i = 0; i < 4; ++i) {
        int m = m0 + ty * 4 + i;
        int n = n0 + tx * 4;
        float c0 = acc[i][0], c1 = acc[i][1], c2 = acc[i][2], c3 = acc[i][3];
        if (sel) {
            c0 += b1[n + 0]; c1 += b1[n + 1];
            c2 += b1[n + 2]; c3 += b1[n + 3];
        }
        float4 o = {c0, c1, c2, c3};
        *(float4*)&out[m * 256 + n] = o;
    }
}

// ---------------------------------------------------------------------------
// Cross kernel (R10 form, FROZEN; batch passed as param): block = 32n x 32m
// tile; thread = 2x2 micro-tile as two f32x2 groups. d chunked 4x64,
// double-buffered smem + register prefetch, one sync per chunk.
// ---------------------------------------------------------------------------
#define SX 34
#define DCH 64

__global__ __launch_bounds__(256, 4) void cross_kernel(
    const float* __restrict__ W2,
    const float* __restrict__ b2,
    float* __restrict__ out,
    int bz)
{
    extern __shared__ float sm[];
    float* xs0 = sm;                     // [2][DCH*SX]
    float* ys0 = sm + 2 * DCH * SX;      // [2][DCH*SX]
    float* ws2 = sm + 4 * DCH * SX;      // [512]

    const int tx = threadIdx.x;        // 0..15 -> m
    const int ty = threadIdx.y;        // 0..15 -> n
    const int t  = ty * 16 + tx;
    const int n0 = blockIdx.y * 32;
    const int m0 = blockIdx.x * 32;

    const float* xp = g_xp  + (bz * NN + n0) * DD;
    const float* yp = g_ypb + (bz * NN + m0) * DD;

    {
        float wv = 0.5f * W2[t];
        u64 wp; PK(wp, wv, wv);
        *(u64*)&ws2[2 * t] = wp;
    }

    u64 C0P, C1P;
    PK(C0P, GC0, GC0);
    PK(C1P, GC1, GC1);

    u64 acc0 = 0ull, acc1 = 0ull;   // (a00,a01), (a10,a11)

    const int r  = t >> 3;    // 0..31
    const int cq = t & 7;     // 0..7

    float4 px[2], py[2];

    // prologue: LDG chunk 0, STS to buffer 0
    #pragma unroll
    for (int it = 0; it < 2; ++it) {
        int dg = 32 * it + 4 * cq;
        px[it] = *(const float4*)&xp[r * 256 + dg];
        py[it] = *(const float4*)&yp[r * 256 + dg];
    }
    #pragma unroll
    for (int it = 0; it < 2; ++it) {
        int dl = 32 * it + 4 * cq;
        xs0[(dl + 0) * SX + r] = px[it].x;
        xs0[(dl + 1) * SX + r] = px[it].y;
        xs0[(dl + 2) * SX + r] = px[it].z;
        xs0[(dl + 3) * SX + r] = px[it].w;
        ys0[(dl + 0) * SX + r] = py[it].x;
        ys0[(dl + 1) * SX + r] = py[it].y;
        ys0[(dl + 2) * SX + r] = py[it].z;
        ys0[(dl + 3) * SX + r] = py[it].w;
    }
    __syncthreads();

    #pragma unroll
    for (int c = 0; c < 4; ++c) {
        const int buf = c & 1;
        const float* xsb = xs0 + buf * DCH * SX;
        const float* ysb = ys0 + buf * DCH * SX;
        const float* xsp = xsb + 2 * ty;
        const float* ysp = ysb + 2 * tx;
        const float* wc  = ws2 + c * 2 * DCH;

        if (c < 3) {
            #pragma unroll
            for (int it = 0; it < 2; ++it) {
                int dg = (c + 1) * DCH + 32 * it + 4 * cq;
                px[it] = *(const float4*)&xp[r * 256 + dg];
                py[it] = *(const float4*)&yp[r * 256 + dg];
            }
        }

        #pragma unroll 8
        for (int d = 0; d < DCH; ++d) {
            float2 xv = *(const float2*)&xsp[d * SX];
            u64 Y = *(const u64*)&ysp[d * SX];
            u64 W = *(const u64*)&wc[2 * d];
            u64 X0, X1;
            PK(X0, xv.x, xv.x);
            PK(X1, xv.y, xv.y);

            #define GEL2(ACC, XB)                               \
            {                                                   \
                u64 H, Q, S, U, T, G;                           \
                float u0, u1, t0, t1;                           \
                F2ADD(H, XB, Y);                                \
                F2MUL(Q, H, H);                                 \
                F2FMA(S, Q, C1P, C0P);                          \
                F2MUL(U, H, S);                                 \
                UNPK(u0, u1, U);                                \
                t0 = tanh_fast(u0);                             \
                t1 = tanh_fast(u1);                             \
                PK(T, t0, t1);                                  \
                F2FMA(G, H, T, H);                              \
                F2FMA(ACC, G, W, ACC);                          \
            }

            GEL2(acc0, X0)
            GEL2(acc1, X1)
            #undef GEL2
        }

        if (c < 3) {
            float* xsn = xs0 + (buf ^ 1) * DCH * SX;
            float* ysn = ys0 + (buf ^ 1) * DCH * SX;
            #pragma unroll
            for (int it = 0; it < 2; ++it) {
                int dl = 32 * it + 4 * cq;
                xsn[(dl + 0) * SX + r] = px[it].x;
                xsn[(dl + 1) * SX + r] = px[it].y;
                xsn[(dl + 2) * SX + r] = px[it].z;
                xsn[(dl + 3) * SX + r] = px[it].w;
                ysn[(dl + 0) * SX + r] = py[it].x;
                ysn[(dl + 1) * SX + r] = py[it].y;
                ysn[(dl + 2) * SX + r] = py[it].z;
                ysn[(dl + 3) * SX + r] = py[it].w;
            }
            __syncthreads();
        }
    }

    const float bb = b2[0];
    u64 bpair; PK(bpair, bb, bb);
    F2ADD(acc0, acc0, bpair);
    F2ADD(acc1, acc1, bpair);

    const int n = n0 + 2 * ty;
    const int m = m0 + 2 * tx;
    float* orow = out + (size_t)(bz * NN + n) * NN + m;
    *(u64*)&orow[0]  = acc0;
    *(u64*)&orow[NN] = acc1;
}

// ---------------------------------------------------------------------------
// Fork-join pipeline: legacy stream runs per-batch GEMMs chained; a second
// (non-blocking) stream runs per-batch cross kernels, each gated on its
// batch's GEMM event; legacy joins on the final event. Under graph capture
// this becomes a 2-branch graph: GEMM(b) hides under cross(b-1).
// ---------------------------------------------------------------------------
extern "C" void kernel_launch(void* const* d_in, const int* in_sizes, int n_in,
                              void* d_out, int out_size)
{
    const float* x  = (const float*)d_in[0];
    const float* y  = (const float*)d_in[1];
    const float* W1 = (const float*)d_in[2];
    const float* b1 = (const float*)d_in[3];
    const float* W2 = (const float*)d_in[4];
    const float* b2 = (const float*)d_in[5];
    float* out = (float*)d_out;

    (void)in_sizes; (void)n_in; (void)out_size;

    const int smem_cross = (4 * DCH * SX + 512) * (int)sizeof(float);
    cudaFuncSetAttribute(cross_kernel,
                         cudaFuncAttributeMaxDynamicSharedMemorySize,
                         smem_cross);

    cudaStream_t s1;
    cudaStreamCreateWithFlags(&s1, cudaStreamNonBlocking);
    cudaEvent_t eg[BATCH], ef;
    for (int b = 0; b < BATCH; ++b)
        cudaEventCreateWithFlags(&eg[b], cudaEventDisableTiming);
    cudaEventCreateWithFlags(&ef, cudaEventDisableTiming);

    dim3 gblk(16, 8);       // 128 threads
    dim3 ggrid(4, 16, 2);   // per-batch: 4 n-tiles x 16 m-tiles x 2 sel
    dim3 cblk(16, 16);
    dim3 cgrid(16, 16, 1);  // per-batch: 16 m-tiles x 16 n-tiles

    // legacy stream: chained per-batch GEMMs, event after each
    for (int b = 0; b < BATCH; ++b) {
        gemm_kernel<<<ggrid, gblk>>>(x, y, W1, b1, b);
        cudaEventRecord(eg[b], 0);
    }
    // side stream: per-batch cross, gated on that batch's GEMM
    for (int b = 0; b < BATCH; ++b) {
        cudaStreamWaitEvent(s1, eg[b], 0);
        cross_kernel<<<cgrid, cblk, smem_cross, s1>>>(W2, b2, out, b);
    }
    cudaEventRecord(ef, s1);
    cudaStreamWaitEvent(0, ef, 0);   // join back into the captured stream
}

// round 14
// speedup vs baseline: 1.1002x; 1.1002x over previous
#include <cuda_runtime.h>
#include <math.h>

#define DD 256
#define BATCH 4
#define NN 512

typedef unsigned long long u64;

// Scratch: xp = x @ Wx  (B*N, D);  ypb = y @ Wy + b1  (B*N, D)
__device__ float g_xp[BATCH * NN * DD];
__device__ float g_ypb[BATCH * NN * DD];
__device__ int   g_flag[4];      // per-d-chunk GEMM completion counters

#define NPROD 64         // producer blocks (32 m-tiles x 2 sel)
#define FLAG_TGT 64      // tiles per 64-wide n-chunk

// ---- f32x2 packed-math primitives ------------------------------------------
#define F2FMA(D_, A_, B_, C_) \
    asm("fma.rn.f32x2 %0, %1, %2, %3;" : "=l"(D_) : "l"(A_), "l"(B_), "l"(C_))
#define F2ADD(D_, A_, B_) \
    asm("add.rn.f32x2 %0, %1, %2;" : "=l"(D_) : "l"(A_), "l"(B_))
#define F2MUL(D_, A_, B_) \
    asm("mul.rn.f32x2 %0, %1, %2;" : "=l"(D_) : "l"(A_), "l"(B_))
#define PK(D_, LO_, HI_) \
    asm("mov.b64 %0, {%1, %2};" : "=l"(D_) : "f"(LO_), "f"(HI_))
#define UNPK(LO_, HI_, S_) \
    asm("mov.b64 {%0, %1}, %2;" : "=f"(LO_), "=f"(HI_) : "l"(S_))

__device__ __forceinline__ float tanh_fast(float v) {
    float r;
    asm("tanh.approx.f32 %0, %1;" : "=f"(r) : "f"(v));
    return r;
}

#define GC0 0.79788456080286536f          // sqrt(2/pi)
#define GC1 0.03567740813636141f          // sqrt(2/pi)*0.044715

#define SX 34       // cross smem row stride
#define DCH 64      // d-chunk

// spin until GEMM chunk c is complete (producers are wave-1 resident)
__device__ __forceinline__ void waitflag(int c) {
    if (threadIdx.x == 0 && threadIdx.y == 0) {
        while (((volatile int*)g_flag)[c] < FLAG_TGT) __nanosleep(128);
    }
    __syncthreads();
}

// ---------------------------------------------------------------------------
// Fused kernel.
// bid < NPROD: producer. p = bid: sel = p>>5, mtile = p&31. Runs the R9 GEMM
//   block body (64x64 tile, BK=16, 256 thr, 4x4 micro) 4 times, n0 = c*64,
//   flagging g_flag[c] after each. Identical FMA order to R9 -> bit-identical.
// bid >= NPROD: consumer. R10 cross tile, chunk prefetch gated on g_flag.
// ---------------------------------------------------------------------------
__global__ __launch_bounds__(256, 4) void fused_kernel(
    const float* __restrict__ x,
    const float* __restrict__ y,
    const float* __restrict__ W1,
    const float* __restrict__ b1,
    const float* __restrict__ W2,
    const float* __restrict__ b2,
    float* __restrict__ out)
{
    extern __shared__ float sm[];
    const int tx = threadIdx.x;     // 0..15
    const int ty = threadIdx.y;     // 0..15
    const int t  = ty * 16 + tx;
    const int bid = blockIdx.x;

    if (bid < NPROD) {
        // ================= PRODUCER (R9 GEMM body x 4 chunks) =============
        float (*As)[16][68] = (float (*)[16][68])sm;              // [2][16][68]
        float (*Bs)[16][68] = (float (*)[16][68])(sm + 2*16*68);  // [2][16][68]

        const int sel  = bid >> 5;
        const int mt   = bid & 31;
        const float* X = sel ? y : x;
        const float* W = sel ? (W1 + 256 * 256) : W1;
        float* outg    = sel ? g_ypb : g_xp;
        const int m0   = mt * 64;

        const int fm = t >> 2;          // A row 0..63
        const int fk = (t & 3) * 4;     // A k quad
        const int gk = t >> 4;          // B k row 0..15
        const int gn = (t & 15) * 4;    // B col quad

        for (int c = 0; c < 4; ++c) {
            const int n0 = c * 64;
            float acc[4][4] = {};

            // K prologue: chunk 0 -> stage 0
            float4 av = *(const float4*)&X[(m0 + fm) * 256 + fk];
            float4 bv = *(const float4*)&W[gk * 256 + n0 + gn];
            As[0][fk + 0][fm] = av.x;
            As[0][fk + 1][fm] = av.y;
            As[0][fk + 2][fm] = av.z;
            As[0][fk + 3][fm] = av.w;
            *(float4*)&Bs[0][gk][gn] = bv;
            __syncthreads();

            for (int kc = 0; kc < 16; ++kc) {
                const int s = kc & 1;
                if (kc < 15) {
                    const int k0 = (kc + 1) * 16;
                    av = *(const float4*)&X[(m0 + fm) * 256 + k0 + fk];
                    bv = *(const float4*)&W[(k0 + gk) * 256 + n0 + gn];
                }
                #pragma unroll
                for (int kk = 0; kk < 16; ++kk) {
                    float4 a = *(const float4*)&As[s][kk][ty * 4];
                    float4 b = *(const float4*)&Bs[s][kk][tx * 4];
                    float avr[4] = {a.x, a.y, a.z, a.w};
                    float bvr[4] = {b.x, b.y, b.z, b.w};
                    #pragma unroll
                    for (int i = 0; i < 4; ++i)
                        #pragma unroll
                        for (int j = 0; j < 4; ++j)
                            acc[i][j] = fmaf(avr[i], bvr[j], acc[i][j]);
                }
                if (kc < 15) {
                    const int s2 = s ^ 1;
                    As[s2][fk + 0][fm] = av.x;
                    As[s2][fk + 1][fm] = av.y;
                    As[s2][fk + 2][fm] = av.z;
                    As[s2][fk + 3][fm] = av.w;
                    *(float4*)&Bs[s2][gk][gn] = bv;
                    __syncthreads();
                }
            }

            #pragma unroll
            for (int i = 0; i < 4; ++i) {
                int m = m0 + ty * 4 + i;
                int n = n0 + tx * 4;
                float c0 = acc[i][0], c1 = acc[i][1];
                float c2 = acc[i][2], c3 = acc[i][3];
                if (sel) {
                    c0 += b1[n + 0]; c1 += b1[n + 1];
                    c2 += b1[n + 2]; c3 += b1[n + 3];
                }
                float4 o = {c0, c1, c2, c3};
                *(float4*)&outg[m * 256 + n] = o;
            }

            __threadfence();       // stores visible at L2
            __syncthreads();       // all threads fenced; smem reusable
            if (t == 0) atomicAdd(&g_flag[c], 1);
        }
        return;
    }

    // ================= CONSUMER (R10 cross + flag gates) ==================
    float* xs0 = sm;                     // [2][DCH*SX]
    float* ys0 = sm + 2 * DCH * SX;      // [2][DCH*SX]
    float* ws2 = sm + 4 * DCH * SX;      // [512]

    const int cid = bid - NPROD;
    const int bz = cid >> 8;
    const int n0 = ((cid >> 4) & 15) * 32;
    const int m0 = (cid & 15) * 32;

    const float* xp = g_xp  + (bz * NN + n0) * DD;
    const float* yp = g_ypb + (bz * NN + m0) * DD;

    {
        float wv = 0.5f * W2[t];
        u64 wp; PK(wp, wv, wv);
        *(u64*)&ws2[2 * t] = wp;
    }

    u64 C0P, C1P;
    PK(C0P, GC0, GC0);
    PK(C1P, GC1, GC1);

    u64 acc0 = 0ull, acc1 = 0ull;   // (a00,a01), (a10,a11)

    const int r  = t >> 3;    // 0..31
    const int cq = t & 7;     // 0..7

    float4 px[2], py[2];

    // prologue: wait chunk 0, LDG (L2-coherent), STS buffer 0
    waitflag(0);
    #pragma unroll
    for (int it = 0; it < 2; ++it) {
        int dg = 32 * it + 4 * cq;
        px[it] = __ldcg((const float4*)&xp[r * 256 + dg]);
        py[it] = __ldcg((const float4*)&yp[r * 256 + dg]);
    }
    #pragma unroll
    for (int it = 0; it < 2; ++it) {
        int dl = 32 * it + 4 * cq;
        xs0[(dl + 0) * SX + r] = px[it].x;
        xs0[(dl + 1) * SX + r] = px[it].y;
        xs0[(dl + 2) * SX + r] = px[it].z;
        xs0[(dl + 3) * SX + r] = px[it].w;
        ys0[(dl + 0) * SX + r] = py[it].x;
        ys0[(dl + 1) * SX + r] = py[it].y;
        ys0[(dl + 2) * SX + r] = py[it].z;
        ys0[(dl + 3) * SX + r] = py[it].w;
    }
    __syncthreads();

    #pragma unroll
    for (int c = 0; c < 4; ++c) {
        const int buf = c & 1;
        const float* xsb = xs0 + buf * DCH * SX;
        const float* ysb = ys0 + buf * DCH * SX;
        const float* xsp = xsb + 2 * ty;
        const float* ysp = ysb + 2 * tx;
        const float* wc  = ws2 + c * 2 * DCH;

        // wait + prefetch chunk c+1 (overlaps compute below)
        if (c < 3) {
            waitflag(c + 1);
            #pragma unroll
            for (int it = 0; it < 2; ++it) {
                int dg = (c + 1) * DCH + 32 * it + 4 * cq;
                px[it] = __ldcg((const float4*)&xp[r * 256 + dg]);
                py[it] = __ldcg((const float4*)&yp[r * 256 + dg]);
            }
        }

        #pragma unroll 8
        for (int d = 0; d < DCH; ++d) {
            float2 xv = *(const float2*)&xsp[d * SX];
            u64 Y = *(const u64*)&ysp[d * SX];
            u64 W = *(const u64*)&wc[2 * d];
            u64 X0, X1;
            PK(X0, xv.x, xv.x);
            PK(X1, xv.y, xv.y);

            #define GEL2(ACC, XB)                               \
            {                                                   \
                u64 H, Q, S, U, T, G;                           \
                float u0, u1, t0, t1;                           \
                F2ADD(H, XB, Y);                                \
                F2MUL(Q, H, H);                                 \
                F2FMA(S, Q, C1P, C0P);                          \
                F2MUL(U, H, S);                                 \
                UNPK(u0, u1, U);                                \
                t0 = tanh_fast(u0);                             \
                t1 = tanh_fast(u1);                             \
                PK(T, t0, t1);                                  \
                F2FMA(G, H, T, H);                              \
                F2FMA(ACC, G, W, ACC);                          \
            }

            GEL2(acc0, X0)
            GEL2(acc1, X1)
            #undef GEL2
        }

        if (c < 3) {
            float* xsn = xs0 + (buf ^ 1) * DCH * SX;
            float* ysn = ys0 + (buf ^ 1) * DCH * SX;
            #pragma unroll
            for (int it = 0; it < 2; ++it) {
                int dl = 32 * it + 4 * cq;
                xsn[(dl + 0) * SX + r] = px[it].x;
                xsn[(dl + 1) * SX + r] = px[it].y;
                xsn[(dl + 2) * SX + r] = px[it].z;
                xsn[(dl + 3) * SX + r] = px[it].w;
                ysn[(dl + 0) * SX + r] = py[it].x;
                ysn[(dl + 1) * SX + r] = py[it].y;
                ysn[(dl + 2) * SX + r] = py[it].z;
                ysn[(dl + 3) * SX + r] = py[it].w;
            }
            __syncthreads();
        }
    }

    const float bb = b2[0];
    u64 bpair; PK(bpair, bb, bb);
    F2ADD(acc0, acc0, bpair);
    F2ADD(acc1, acc1, bpair);

    const int n = n0 + 2 * ty;
    const int m = m0 + 2 * tx;
    float* orow = out + (size_t)(bz * NN + n) * NN + m;
    *(u64*)&orow[0]  = acc0;
    *(u64*)&orow[NN] = acc1;
}

// ---------------------------------------------------------------------------
extern "C" void kernel_launch(void* const* d_in, const int* in_sizes, int n_in,
                              void* d_out, int out_size)
{
    const float* x  = (const float*)d_in[0];
    const float* y  = (const float*)d_in[1];
    const float* W1 = (const float*)d_in[2];
    const float* b1 = (const float*)d_in[3];
    const float* W2 = (const float*)d_in[4];
    const float* b2 = (const float*)d_in[5];
    float* out = (float*)d_out;

    (void)in_sizes; (void)n_in; (void)out_size;

    // reset chunk flags (graph node preceding the fused kernel each replay)
    void* flagp = nullptr;
    cudaGetSymbolAddress(&flagp, g_flag);
    cudaMemsetAsync(flagp, 0, 4 * sizeof(int));

    // consumer smem (35.3KB) > producer smem (17.4KB): size for consumer
    const int smem_bytes = (4 * DCH * SX + 512) * (int)sizeof(float);
    cudaFuncSetAttribute(fused_kernel,
                         cudaFuncAttributeMaxDynamicSharedMemorySize,
                         smem_bytes);

    dim3 blk(16, 16);
    fused_kernel<<<NPROD + 16 * 16 * BATCH, blk, smem_bytes>>>(
        x, y, W1, b1, W2, b2, out);
}

// round 15
// speedup vs baseline: 1.2863x; 1.1691x over previous
#include <cuda_runtime.h>
#include <math.h>

#define DD 256
#define BATCH 4
#define NN 512

typedef unsigned long long u64;

// Scratch: xp = x @ Wx  (B*N, D);  ypb = y @ Wy + b1  (B*N, D)
__device__ float g_xp[BATCH * NN * DD];
__device__ float g_ypb[BATCH * NN * DD];

// ---- f32x2 packed-math primitives ------------------------------------------
#define F2FMA(D_, A_, B_, C_) \
    asm("fma.rn.f32x2 %0, %1, %2, %3;" : "=l"(D_) : "l"(A_), "l"(B_), "l"(C_))
#define F2ADD(D_, A_, B_) \
    asm("add.rn.f32x2 %0, %1, %2;" : "=l"(D_) : "l"(A_), "l"(B_))
#define F2MUL(D_, A_, B_) \
    asm("mul.rn.f32x2 %0, %1, %2;" : "=l"(D_) : "l"(A_), "l"(B_))
#define PK(D_, LO_, HI_) \
    asm("mov.b64 %0, {%1, %2};" : "=l"(D_) : "f"(LO_), "f"(HI_))
#define UNPK(LO_, HI_, S_) \
    asm("mov.b64 {%0, %1}, %2;" : "=f"(LO_), "=f"(HI_) : "l"(S_))

__device__ __forceinline__ float tanh_fast(float v) {
    float r;
    asm("tanh.approx.f32 %0, %1;" : "=f"(r) : "f"(v));
    return r;
}

#define GC0 0.79788456080286536f          // sqrt(2/pi)
#define GC1 0.03567740813636141f          // sqrt(2/pi)*0.044715

// ---------------------------------------------------------------------------
// Merged GEMM: z=0: g_xp = x @ W1[0:256];  z=1: g_ypb = y @ W1[256:512] + b1
// Tiles 64(m) x 128(n), BK=16, 256 threads. Thread = 4m (two m-pairs) x 8n,
// f32x2 accumulators paired along m:
//   A: one double2 LDS.128 of transposed As -> two (A[m],A[m+1]) u64, no packs
//   B: pre-duplicated smem Bd[k][2n]=(b,b) -> 4x LDS.128 broadcast (2 addrs/warp)
// LDS 6 wf/warp-kk < fma 16 F2FMA -> fma-bound at f32x2 rate.
// Double-buffered smem + register prefetch, 1 sync/chunk.
// Grid (2, 32, 2) = 128 blocks -> 1 block/SM, single wave.
// ---------------------------------------------------------------------------
__global__ __launch_bounds__(256) void gemm_kernel(
    const float* __restrict__ x,
    const float* __restrict__ y,
    const float* __restrict__ W1,
    const float* __restrict__ b1)
{
    __shared__ float As[2][16][68];    // [stage][k][m] transposed, 64 m + pad
    __shared__ float Bd[2][16][260];   // [stage][k][2n] duplicated, 128 n + pad

    const int sel = blockIdx.z;
    const float* X = sel ? y : x;
    const float* W = sel ? (W1 + 256 * 256) : W1;
    float* out = sel ? g_ypb : g_xp;

    const int tx = threadIdx.x;     // 0..15
    const int ty = threadIdx.y;     // 0..15
    const int t  = ty * 16 + tx;
    const int m0 = blockIdx.y * 64;
    const int n0 = blockIdx.x * 128;

    // fill roles
    const int fm = t >> 2;          // A row 0..63
    const int fk = (t & 3) * 4;     // A k quad
    const int bk = t >> 4;          // B k row 0..15
    const int bn = (t & 15) * 8;    // B col octet base

    // compute roles
    const int mg = t & 15;          // m base = 4*mg (two pairs)
    const int ng = t >> 4;          // n base = 8*ng

    u64 acc[2][8];
    #pragma unroll
    for (int mp = 0; mp < 2; ++mp)
        #pragma unroll
        for (int nj = 0; nj < 8; ++nj) acc[mp][nj] = 0ull;

    // prologue: chunk 0 -> stage 0
    float4 av  = *(const float4*)&X[(m0 + fm) * 256 + fk];
    float4 bw0 = *(const float4*)&W[bk * 256 + n0 + bn];
    float4 bw1 = *(const float4*)&W[bk * 256 + n0 + bn + 4];
    {
        As[0][fk + 0][fm] = av.x;
        As[0][fk + 1][fm] = av.y;
        As[0][fk + 2][fm] = av.z;
        As[0][fk + 3][fm] = av.w;
        float4 d0 = {bw0.x, bw0.x, bw0.y, bw0.y};
        float4 d1 = {bw0.z, bw0.z, bw0.w, bw0.w};
        float4 d2 = {bw1.x, bw1.x, bw1.y, bw1.y};
        float4 d3 = {bw1.z, bw1.z, bw1.w, bw1.w};
        *(float4*)&Bd[0][bk][2 * bn + 0]  = d0;
        *(float4*)&Bd[0][bk][2 * bn + 4]  = d1;
        *(float4*)&Bd[0][bk][2 * bn + 8]  = d2;
        *(float4*)&Bd[0][bk][2 * bn + 12] = d3;
    }
    __syncthreads();

    for (int kc = 0; kc < 16; ++kc) {
        const int s = kc & 1;
        if (kc < 15) {
            const int k0 = (kc + 1) * 16;
            av  = *(const float4*)&X[(m0 + fm) * 256 + k0 + fk];
            bw0 = *(const float4*)&W[(k0 + bk) * 256 + n0 + bn];
            bw1 = *(const float4*)&W[(k0 + bk) * 256 + n0 + bn + 4];
        }

        #pragma unroll
        for (int kk = 0; kk < 16; ++kk) {
            double2 ad = *(const double2*)&As[s][kk][4 * mg];   // LDS.128
            u64 A0 = __double_as_longlong(ad.x);   // (A[4mg],   A[4mg+1])
            u64 A1 = __double_as_longlong(ad.y);   // (A[4mg+2], A[4mg+3])
            const float* bp = &Bd[s][kk][16 * ng];
            double2 b01 = *(const double2*)&bp[0];    // (b0,b0),(b1,b1)
            double2 b23 = *(const double2*)&bp[4];
            double2 b45 = *(const double2*)&bp[8];
            double2 b67 = *(const double2*)&bp[12];
            u64 B[8];
            B[0] = __double_as_longlong(b01.x);
            B[1] = __double_as_longlong(b01.y);
            B[2] = __double_as_longlong(b23.x);
            B[3] = __double_as_longlong(b23.y);
            B[4] = __double_as_longlong(b45.x);
            B[5] = __double_as_longlong(b45.y);
            B[6] = __double_as_longlong(b67.x);
            B[7] = __double_as_longlong(b67.y);
            #pragma unroll
            for (int nj = 0; nj < 8; ++nj) {
                F2FMA(acc[0][nj], A0, B[nj], acc[0][nj]);
                F2FMA(acc[1][nj], A1, B[nj], acc[1][nj]);
            }
        }

        if (kc < 15) {
            const int s2 = s ^ 1;
            As[s2][fk + 0][fm] = av.x;
            As[s2][fk + 1][fm] = av.y;
            As[s2][fk + 2][fm] = av.z;
            As[s2][fk + 3][fm] = av.w;
            float4 d0 = {bw0.x, bw0.x, bw0.y, bw0.y};
            float4 d1 = {bw0.z, bw0.z, bw0.w, bw0.w};
            float4 d2 = {bw1.x, bw1.x, bw1.y, bw1.y};
            float4 d3 = {bw1.z, bw1.z, bw1.w, bw1.w};
            *(float4*)&Bd[s2][bk][2 * bn + 0]  = d0;
            *(float4*)&Bd[s2][bk][2 * bn + 4]  = d1;
            *(float4*)&Bd[s2][bk][2 * bn + 8]  = d2;
            *(float4*)&Bd[s2][bk][2 * bn + 12] = d3;
            __syncthreads();
        }
    }

    // epilogue: 4 rows (2 pairs) x 8 cols per thread
    const int nb = n0 + 8 * ng;
    #pragma unroll
    for (int mp = 0; mp < 2; ++mp) {
        const int m = m0 + 4 * mg + 2 * mp;
        float lo[8], hi[8];
        #pragma unroll
        for (int nj = 0; nj < 8; ++nj) UNPK(lo[nj], hi[nj], acc[mp][nj]);
        if (sel) {
            #pragma unroll
            for (int nj = 0; nj < 8; ++nj) {
                float bv = b1[nb + nj];
                lo[nj] += bv;
                hi[nj] += bv;
            }
        }
        float4 o;
        o.x = lo[0]; o.y = lo[1]; o.z = lo[2]; o.w = lo[3];
        *(float4*)&out[m * 256 + nb] = o;
        o.x = lo[4]; o.y = lo[5]; o.z = lo[6]; o.w = lo[7];
        *(float4*)&out[m * 256 + nb + 4] = o;
        o.x = hi[0]; o.y = hi[1]; o.z = hi[2]; o.w = hi[3];
        *(float4*)&out[(m + 1) * 256 + nb] = o;
        o.x = hi[4]; o.y = hi[5]; o.z = hi[6]; o.w = hi[7];
        *(float4*)&out[(m + 1) * 256 + nb + 4] = o;
    }
}

// ---------------------------------------------------------------------------
// Cross kernel (R10 form, FROZEN): block = (b, 32n x 32m) tile; thread = 2x2
// micro-tile as two f32x2 groups. d chunked 4x64, double-buffered smem +
// register prefetch, one sync per chunk.
// ---------------------------------------------------------------------------
#define SX 34
#define DCH 64

__global__ __launch_bounds__(256, 4) void cross_kernel(
    const float* __restrict__ W2,
    const float* __restrict__ b2,
    float* __restrict__ out)
{
    extern __shared__ float sm[];
    float* xs0 = sm;                     // [2][DCH*SX]
    float* ys0 = sm + 2 * DCH * SX;      // [2][DCH*SX]
    float* ws2 = sm + 4 * DCH * SX;      // [512]

    const int tx = threadIdx.x;        // 0..15 -> m
    const int ty = threadIdx.y;        // 0..15 -> n
    const int t  = ty * 16 + tx;
    const int bz = blockIdx.z;
    const int n0 = blockIdx.y * 32;
    const int m0 = blockIdx.x * 32;

    const float* xp = g_xp  + (bz * NN + n0) * DD;
    const float* yp = g_ypb + (bz * NN + m0) * DD;

    {
        float wv = 0.5f * W2[t];
        u64 wp; PK(wp, wv, wv);
        *(u64*)&ws2[2 * t] = wp;
    }

    u64 C0P, C1P;
    PK(C0P, GC0, GC0);
    PK(C1P, GC1, GC1);

    u64 acc0 = 0ull, acc1 = 0ull;   // (a00,a01), (a10,a11)

    const int r  = t >> 3;    // 0..31
    const int cq = t & 7;     // 0..7

    float4 px[2], py[2];

    // prologue: LDG chunk 0, STS to buffer 0
    #pragma unroll
    for (int it = 0; it < 2; ++it) {
        int dg = 32 * it + 4 * cq;
        px[it] = *(const float4*)&xp[r * 256 + dg];
        py[it] = *(const float4*)&yp[r * 256 + dg];
    }
    #pragma unroll
    for (int it = 0; it < 2; ++it) {
        int dl = 32 * it + 4 * cq;
        xs0[(dl + 0) * SX + r] = px[it].x;
        xs0[(dl + 1) * SX + r] = px[it].y;
        xs0[(dl + 2) * SX + r] = px[it].z;
        xs0[(dl + 3) * SX + r] = px[it].w;
        ys0[(dl + 0) * SX + r] = py[it].x;
        ys0[(dl + 1) * SX + r] = py[it].y;
        ys0[(dl + 2) * SX + r] = py[it].z;
        ys0[(dl + 3) * SX + r] = py[it].w;
    }
    __syncthreads();

    #pragma unroll
    for (int c = 0; c < 4; ++c) {
        const int buf = c & 1;
        const float* xsb = xs0 + buf * DCH * SX;
        const float* ysb = ys0 + buf * DCH * SX;
        const float* xsp = xsb + 2 * ty;
        const float* ysp = ysb + 2 * tx;
        const float* wc  = ws2 + c * 2 * DCH;

        if (c < 3) {
            #pragma unroll
            for (int it = 0; it < 2; ++it) {
                int dg = (c + 1) * DCH + 32 * it + 4 * cq;
                px[it] = *(const float4*)&xp[r * 256 + dg];
                py[it] = *(const float4*)&yp[r * 256 + dg];
            }
        }

        #pragma unroll 8
        for (int d = 0; d < DCH; ++d) {
            float2 xv = *(const float2*)&xsp[d * SX];
            u64 Y = *(const u64*)&ysp[d * SX];
            u64 W = *(const u64*)&wc[2 * d];
            u64 X0, X1;
            PK(X0, xv.x, xv.x);
            PK(X1, xv.y, xv.y);

            #define GEL2(ACC, XB)                               \
            {                                                   \
                u64 H, Q, S, U, T, G;                           \
                float u0, u1, t0, t1;                           \
                F2ADD(H, XB, Y);                                \
                F2MUL(Q, H, H);                                 \
                F2FMA(S, Q, C1P, C0P);                          \
                F2MUL(U, H, S);                                 \
                UNPK(u0, u1, U);                                \
                t0 = tanh_fast(u0);                             \
                t1 = tanh_fast(u1);                             \
                PK(T, t0, t1);                                  \
                F2FMA(G, H, T, H);                              \
                F2FMA(ACC, G, W, ACC);                          \
            }

            GEL2(acc0, X0)
            GEL2(acc1, X1)
            #undef GEL2
        }

        if (c < 3) {
            float* xsn = xs0 + (buf ^ 1) * DCH * SX;
            float* ysn = ys0 + (buf ^ 1) * DCH * SX;
            #pragma unroll
            for (int it = 0; it < 2; ++it) {
                int dl = 32 * it + 4 * cq;
                xsn[(dl + 0) * SX + r] = px[it].x;
                xsn[(dl + 1) * SX + r] = px[it].y;
                xsn[(dl + 2) * SX + r] = px[it].z;
                xsn[(dl + 3) * SX + r] = px[it].w;
                ysn[(dl + 0) * SX + r] = py[it].x;
                ysn[(dl + 1) * SX + r] = py[it].y;
                ysn[(dl + 2) * SX + r] = py[it].z;
                ysn[(dl + 3) * SX + r] = py[it].w;
            }
            __syncthreads();
        }
    }

    const float bb = b2[0];
    u64 bpair; PK(bpair, bb, bb);
    F2ADD(acc0, acc0, bpair);
    F2ADD(acc1, acc1, bpair);

    const int n = n0 + 2 * ty;
    const int m = m0 + 2 * tx;
    float* orow = out + (size_t)(bz * NN + n) * NN + m;
    *(u64*)&orow[0]  = acc0;
    *(u64*)&orow[NN] = acc1;
}

// ---------------------------------------------------------------------------
extern "C" void kernel_launch(void* const* d_in, const int* in_sizes, int n_in,
                              void* d_out, int out_size)
{
    const float* x  = (const float*)d_in[0];
    const float* y  = (const float*)d_in[1];
    const float* W1 = (const float*)d_in[2];
    const float* b1 = (const float*)d_in[3];
    const float* W2 = (const float*)d_in[4];
    const float* b2 = (const float*)d_in[5];
    float* out = (float*)d_out;

    (void)in_sizes; (void)n_in; (void)out_size;

    const int smem_cross = (4 * DCH * SX + 512) * (int)sizeof(float);
    cudaFuncSetAttribute(cross_kernel,
                         cudaFuncAttributeMaxDynamicSharedMemorySize,
                         smem_cross);

    dim3 gblk(16, 16);      // 256 threads
    dim3 ggrid(2, 32, 2);   // 128 blocks: 2 n-tiles x 32 m-tiles x 2 gemms
    gemm_kernel<<<ggrid, gblk>>>(x, y, W1, b1);

    dim3 cblk(16, 16);
    dim3 cgrid(16, 16, 4);  // (m-tiles, n-tiles, batch)
    cross_kernel<<<cgrid, cblk, smem_cross>>>(W2, b2, out);
}

// round 16
// speedup vs baseline: 1.3038x; 1.0136x over previous
#include <cuda_runtime.h>
#include <math.h>

#define DD 256
#define BATCH 4
#define NN 512

typedef unsigned long long u64;

// Scratch: xp = x @ Wx  (B*N, D);  ypb = y @ Wy + b1  (B*N, D)
__device__ float g_xp[BATCH * NN * DD];
__device__ float g_ypb[BATCH * NN * DD];

// ---- f32x2 packed-math primitives ------------------------------------------
#define F2FMA(D_, A_, B_, C_) \
    asm("fma.rn.f32x2 %0, %1, %2, %3;" : "=l"(D_) : "l"(A_), "l"(B_), "l"(C_))
#define F2ADD(D_, A_, B_) \
    asm("add.rn.f32x2 %0, %1, %2;" : "=l"(D_) : "l"(A_), "l"(B_))
#define F2MUL(D_, A_, B_) \
    asm("mul.rn.f32x2 %0, %1, %2;" : "=l"(D_) : "l"(A_), "l"(B_))
#define PK(D_, LO_, HI_) \
    asm("mov.b64 %0, {%1, %2};" : "=l"(D_) : "f"(LO_), "f"(HI_))
#define UNPK(LO_, HI_, S_) \
    asm("mov.b64 {%0, %1}, %2;" : "=f"(LO_), "=f"(HI_) : "l"(S_))

__device__ __forceinline__ float tanh_fast(float v) {
    float r;
    asm("tanh.approx.f32 %0, %1;" : "=f"(r) : "f"(v));
    return r;
}

#define GC0 0.79788456080286536f          // sqrt(2/pi)
#define GC1 0.03567740813636141f          // sqrt(2/pi)*0.044715

// ---------------------------------------------------------------------------
// Merged GEMM: z=0: g_xp = x @ W1[0:256];  z=1: g_ypb = y @ W1[256:512] + b1
// R9 structure: 64x64 tiles, BK=16, 256 threads, 256 blocks (2/SM), double-
// buffered smem + register prefetch, 1 sync/chunk.
// f32x2 inner with 4-wavefront LDS:
//   A: transposed As; one double2 LDS.128 -> two natural (a_m, a_m+1) pairs
//      (16 lanes x 16B contiguous = 2 wf), zero packs.
//   B: duplicated Bd[k][2n]=(b,b); two LDS.128, 2 distinct addrs/warp
//      (broadcast, 1 wf each) -> four (b,b) u64 operands, zero packs.
// Per warp-kk: 3 LDS + 8 F2FMA. fma 64 cyc/SM-kk = LDS 64 -> balanced,
// half the scalar fma bound. k-ascending fma per lane -> bit-identical to R9.
// ---------------------------------------------------------------------------
__global__ __launch_bounds__(256) void gemm_kernel(
    const float* __restrict__ x,
    const float* __restrict__ y,
    const float* __restrict__ W1,
    const float* __restrict__ b1)
{
    __shared__ float As[2][16][68];    // [stage][k][m] transposed (272B rows)
    __shared__ float Bd[2][16][136];   // [stage][k][2n] duplicated (544B rows)

    const int sel = blockIdx.z;
    const float* X = sel ? y : x;
    const float* W = sel ? (W1 + 256 * 256) : W1;
    float* out = sel ? g_ypb : g_xp;

    const int tx = threadIdx.x;     // 0..15
    const int ty = threadIdx.y;     // 0..15
    const int t  = ty * 16 + tx;
    const int m0 = blockIdx.y * 64;
    const int n0 = blockIdx.x * 64;

    // fill roles
    const int fm = t >> 2;          // A row 0..63
    const int fk = (t & 3) * 4;     // A k quad
    const int bk = t >> 4;          // B k row 0..15
    const int gn = (t & 15) * 4;    // B col quad base

    // compute roles
    const int mg = t & 15;          // m base 4*mg (rows 4mg..4mg+3)
    const int nq = t >> 4;          // n base 4*nq

    u64 acc[2][4];
    #pragma unroll
    for (int mp = 0; mp < 2; ++mp)
        #pragma unroll
        for (int nj = 0; nj < 4; ++nj) acc[mp][nj] = 0ull;

    // prologue: chunk 0 -> stage 0
    float4 av = *(const float4*)&X[(m0 + fm) * 256 + fk];
    float4 bw = *(const float4*)&W[bk * 256 + n0 + gn];
    {
        As[0][fk + 0][fm] = av.x;
        As[0][fk + 1][fm] = av.y;
        As[0][fk + 2][fm] = av.z;
        As[0][fk + 3][fm] = av.w;
        float4 d0 = {bw.x, bw.x, bw.y, bw.y};
        float4 d1 = {bw.z, bw.z, bw.w, bw.w};
        *(float4*)&Bd[0][bk][2 * gn]     = d0;
        *(float4*)&Bd[0][bk][2 * gn + 4] = d1;
    }
    __syncthreads();

    for (int kc = 0; kc < 16; ++kc) {
        const int s = kc & 1;
        if (kc < 15) {
            const int k0 = (kc + 1) * 16;
            av = *(const float4*)&X[(m0 + fm) * 256 + k0 + fk];
            bw = *(const float4*)&W[(k0 + bk) * 256 + n0 + gn];
        }

        #pragma unroll
        for (int kk = 0; kk < 16; ++kk) {
            double2 ad = *(const double2*)&As[s][kk][4 * mg];   // LDS.128
            u64 A0 = __double_as_longlong(ad.x);   // (A[4mg],   A[4mg+1])
            u64 A1 = __double_as_longlong(ad.y);   // (A[4mg+2], A[4mg+3])
            const float* br = &Bd[s][kk][8 * nq];
            double2 bq0 = *(const double2*)&br[0];  // (b0,b0),(b1,b1)
            double2 bq1 = *(const double2*)&br[4];  // (b2,b2),(b3,b3)
            u64 B0 = __double_as_longlong(bq0.x);
            u64 B1 = __double_as_longlong(bq0.y);
            u64 B2 = __double_as_longlong(bq1.x);
            u64 B3 = __double_as_longlong(bq1.y);
            F2FMA(acc[0][0], A0, B0, acc[0][0]);
            F2FMA(acc[0][1], A0, B1, acc[0][1]);
            F2FMA(acc[0][2], A0, B2, acc[0][2]);
            F2FMA(acc[0][3], A0, B3, acc[0][3]);
            F2FMA(acc[1][0], A1, B0, acc[1][0]);
            F2FMA(acc[1][1], A1, B1, acc[1][1]);
            F2FMA(acc[1][2], A1, B2, acc[1][2]);
            F2FMA(acc[1][3], A1, B3, acc[1][3]);
        }

        if (kc < 15) {
            const int s2 = s ^ 1;
            As[s2][fk + 0][fm] = av.x;
            As[s2][fk + 1][fm] = av.y;
            As[s2][fk + 2][fm] = av.z;
            As[s2][fk + 3][fm] = av.w;
            float4 d0 = {bw.x, bw.x, bw.y, bw.y};
            float4 d1 = {bw.z, bw.z, bw.w, bw.w};
            *(float4*)&Bd[s2][bk][2 * gn]     = d0;
            *(float4*)&Bd[s2][bk][2 * gn + 4] = d1;
            __syncthreads();
        }
    }

    // epilogue: rows 4mg..4mg+3, cols 4nq..4nq+3
    const int n = n0 + 4 * nq;
    float bias[4] = {0.f, 0.f, 0.f, 0.f};
    if (sel) {
        float4 bv4 = *(const float4*)&b1[n];
        bias[0] = bv4.x; bias[1] = bv4.y; bias[2] = bv4.z; bias[3] = bv4.w;
    }
    #pragma unroll
    for (int mp = 0; mp < 2; ++mp) {
        const int m = m0 + 4 * mg + 2 * mp;
        float lo[4], hi[4];
        #pragma unroll
        for (int nj = 0; nj < 4; ++nj) {
            UNPK(lo[nj], hi[nj], acc[mp][nj]);
            lo[nj] += bias[nj];
            hi[nj] += bias[nj];
        }
        float4 o0 = {lo[0], lo[1], lo[2], lo[3]};
        float4 o1 = {hi[0], hi[1], hi[2], hi[3]};
        *(float4*)&out[m * 256 + n]       = o0;
        *(float4*)&out[(m + 1) * 256 + n] = o1;
    }
}

// ---------------------------------------------------------------------------
// Cross kernel (R10 form, FROZEN): block = (b, 32n x 32m) tile; thread = 2x2
// micro-tile as two f32x2 groups. d chunked 4x64, double-buffered smem +
// register prefetch, one sync per chunk.
// ---------------------------------------------------------------------------
#define SX 34
#define DCH 64

__global__ __launch_bounds__(256, 4) void cross_kernel(
    const float* __restrict__ W2,
    const float* __restrict__ b2,
    float* __restrict__ out)
{
    extern __shared__ float sm[];
    float* xs0 = sm;                     // [2][DCH*SX]
    float* ys0 = sm + 2 * DCH * SX;      // [2][DCH*SX]
    float* ws2 = sm + 4 * DCH * SX;      // [512]

    const int tx = threadIdx.x;        // 0..15 -> m
    const int ty = threadIdx.y;        // 0..15 -> n
    const int t  = ty * 16 + tx;
    const int bz = blockIdx.z;
    const int n0 = blockIdx.y * 32;
    const int m0 = blockIdx.x * 32;

    const float* xp = g_xp  + (bz * NN + n0) * DD;
    const float* yp = g_ypb + (bz * NN + m0) * DD;

    {
        float wv = 0.5f * W2[t];
        u64 wp; PK(wp, wv, wv);
        *(u64*)&ws2[2 * t] = wp;
    }

    u64 C0P, C1P;
    PK(C0P, GC0, GC0);
    PK(C1P, GC1, GC1);

    u64 acc0 = 0ull, acc1 = 0ull;   // (a00,a01), (a10,a11)

    const int r  = t >> 3;    // 0..31
    const int cq = t & 7;     // 0..7

    float4 px[2], py[2];

    // prologue: LDG chunk 0, STS to buffer 0
    #pragma unroll
    for (int it = 0; it < 2; ++it) {
        int dg = 32 * it + 4 * cq;
        px[it] = *(const float4*)&xp[r * 256 + dg];
        py[it] = *(const float4*)&yp[r * 256 + dg];
    }
    #pragma unroll
    for (int it = 0; it < 2; ++it) {
        int dl = 32 * it + 4 * cq;
        xs0[(dl + 0) * SX + r] = px[it].x;
        xs0[(dl + 1) * SX + r] = px[it].y;
        xs0[(dl + 2) * SX + r] = px[it].z;
        xs0[(dl + 3) * SX + r] = px[it].w;
        ys0[(dl + 0) * SX + r] = py[it].x;
        ys0[(dl + 1) * SX + r] = py[it].y;
        ys0[(dl + 2) * SX + r] = py[it].z;
        ys0[(dl + 3) * SX + r] = py[it].w;
    }
    __syncthreads();

    #pragma unroll
    for (int c = 0; c < 4; ++c) {
        const int buf = c & 1;
        const float* xsb = xs0 + buf * DCH * SX;
        const float* ysb = ys0 + buf * DCH * SX;
        const float* xsp = xsb + 2 * ty;
        const float* ysp = ysb + 2 * tx;
        const float* wc  = ws2 + c * 2 * DCH;

        if (c < 3) {
            #pragma unroll
            for (int it = 0; it < 2; ++it) {
                int dg = (c + 1) * DCH + 32 * it + 4 * cq;
                px[it] = *(const float4*)&xp[r * 256 + dg];
                py[it] = *(const float4*)&yp[r * 256 + dg];
            }
        }

        #pragma unroll 8
        for (int d = 0; d < DCH; ++d) {
            float2 xv = *(const float2*)&xsp[d * SX];
            u64 Y = *(const u64*)&ysp[d * SX];
            u64 W = *(const u64*)&wc[2 * d];
            u64 X0, X1;
            PK(X0, xv.x, xv.x);
            PK(X1, xv.y, xv.y);

            #define GEL2(ACC, XB)                               \
            {                                                   \
                u64 H, Q, S, U, T, G;                           \
                float u0, u1, t0, t1;                           \
                F2ADD(H, XB, Y);                                \
                F2MUL(Q, H, H);                                 \
                F2FMA(S, Q, C1P, C0P);                          \
                F2MUL(U, H, S);                                 \
                UNPK(u0, u1, U);                                \
                t0 = tanh_fast(u0);                             \
                t1 = tanh_fast(u1);                             \
                PK(T, t0, t1);                                  \
                F2FMA(G, H, T, H);                              \
                F2FMA(ACC, G, W, ACC);                          \
            }

            GEL2(acc0, X0)
            GEL2(acc1, X1)
            #undef GEL2
        }

        if (c < 3) {
            float* xsn = xs0 + (buf ^ 1) * DCH * SX;
            float* ysn = ys0 + (buf ^ 1) * DCH * SX;
            #pragma unroll
            for (int it = 0; it < 2; ++it) {
                int dl = 32 * it + 4 * cq;
                xsn[(dl + 0) * SX + r] = px[it].x;
                xsn[(dl + 1) * SX + r] = px[it].y;
                xsn[(dl + 2) * SX + r] = px[it].z;
                xsn[(dl + 3) * SX + r] = px[it].w;
                ysn[(dl + 0) * SX + r] = py[it].x;
                ysn[(dl + 1) * SX + r] = py[it].y;
                ysn[(dl + 2) * SX + r] = py[it].z;
                ysn[(dl + 3) * SX + r] = py[it].w;
            }
            __syncthreads();
        }
    }

    const float bb = b2[0];
    u64 bpair; PK(bpair, bb, bb);
    F2ADD(acc0, acc0, bpair);
    F2ADD(acc1, acc1, bpair);

    const int n = n0 + 2 * ty;
    const int m = m0 + 2 * tx;
    float* orow = out + (size_t)(bz * NN + n) * NN + m;
    *(u64*)&orow[0]  = acc0;
    *(u64*)&orow[NN] = acc1;
}

// ---------------------------------------------------------------------------
extern "C" void kernel_launch(void* const* d_in, const int* in_sizes, int n_in,
                              void* d_out, int out_size)
{
    const float* x  = (const float*)d_in[0];
    const float* y  = (const float*)d_in[1];
    const float* W1 = (const float*)d_in[2];
    const float* b1 = (const float*)d_in[3];
    const float* W2 = (const float*)d_in[4];
    const float* b2 = (const float*)d_in[5];
    float* out = (float*)d_out;

    (void)in_sizes; (void)n_in; (void)out_size;

    const int smem_cross = (4 * DCH * SX + 512) * (int)sizeof(float);
    cudaFuncSetAttribute(cross_kernel,
                         cudaFuncAttributeMaxDynamicSharedMemorySize,
                         smem_cross);

    dim3 gblk(16, 16);      // 256 threads
    dim3 ggrid(4, 32, 2);   // 256 blocks (2/SM), both GEMMs in one launch
    gemm_kernel<<<ggrid, gblk>>>(x, y, W1, b1);

    dim3 cblk(16, 16);
    dim3 cgrid(16, 16, 4);  // (m-tiles, n-tiles, batch)
    cross_kernel<<<cgrid, cblk, smem_cross>>>(W2, b2, out);
}

// round 17
// speedup vs baseline: 1.4144x; 1.0848x over previous
#include <cuda_runtime.h>
#include <math.h>

#define DD 256
#define BATCH 4
#define NN 512

typedef unsigned long long u64;

// Scratch: xp = x @ Wx  (B*N, D);  ypb = y @ Wy + b1  (B*N, D)
__device__ float g_xp[BATCH * NN * DD];
__device__ float g_ypb[BATCH * NN * DD];

// ---- f32x2 packed-math primitives ------------------------------------------
#define F2FMA(D_, A_, B_, C_) \
    asm("fma.rn.f32x2 %0, %1, %2, %3;" : "=l"(D_) : "l"(A_), "l"(B_), "l"(C_))
#define F2ADD(D_, A_, B_) \
    asm("add.rn.f32x2 %0, %1, %2;" : "=l"(D_) : "l"(A_), "l"(B_))
#define F2MUL(D_, A_, B_) \
    asm("mul.rn.f32x2 %0, %1, %2;" : "=l"(D_) : "l"(A_), "l"(B_))
#define PK(D_, LO_, HI_) \
    asm("mov.b64 %0, {%1, %2};" : "=l"(D_) : "f"(LO_), "f"(HI_))
#define UNPK(LO_, HI_, S_) \
    asm("mov.b64 {%0, %1}, %2;" : "=f"(LO_), "=f"(HI_) : "l"(S_))

__device__ __forceinline__ float tanh_fast(float v) {
    float r;
    asm("tanh.approx.f32 %0, %1;" : "=f"(r) : "f"(v));
    return r;
}

#define GC0 0.79788456080286536f          // sqrt(2/pi)
#define GC1 0.03567740813636141f          // sqrt(2/pi)*0.044715

// ---------------------------------------------------------------------------
// Merged GEMM (R9 scalar form, FROZEN): z=0: g_xp = x @ W1[0:256];
// z=1: g_ypb = y @ W1[256:512] + b1. 64x64 tiles, BK=16, 256 threads, 4x4
// micro-tile, double-buffered smem + register prefetch, 1 sync per K-chunk.
// Ends with a PDL trigger so the cross kernel's blocks can get resident.
// ---------------------------------------------------------------------------
__global__ __launch_bounds__(256) void gemm_kernel(
    const float* __restrict__ x,
    const float* __restrict__ y,
    const float* __restrict__ W1,
    const float* __restrict__ b1)
{
    __shared__ float As[2][16][68];   // [stage][k][m] (A transposed)
    __shared__ float Bs[2][16][68];   // [stage][k][n]

    const int sel = blockIdx.z;
    const float* X = sel ? y : x;
    const float* W = sel ? (W1 + 256 * 256) : W1;
    float* out = sel ? g_ypb : g_xp;

    const int tx = threadIdx.x;     // 0..15
    const int ty = threadIdx.y;     // 0..15
    const int t  = ty * 16 + tx;
    const int m0 = blockIdx.y * 64;
    const int n0 = blockIdx.x * 64;

    // fill roles
    const int fm = t >> 2;          // A row 0..63
    const int fk = (t & 3) * 4;     // A k quad
    const int gk = t >> 4;          // B k row 0..15
    const int gn = (t & 15) * 4;    // B col quad

    float acc[4][4] = {};

    // prologue: chunk 0 -> stage 0
    float4 av = *(const float4*)&X[(m0 + fm) * 256 + fk];
    float4 bv = *(const float4*)&W[gk * 256 + n0 + gn];
    As[0][fk + 0][fm] = av.x;
    As[0][fk + 1][fm] = av.y;
    As[0][fk + 2][fm] = av.z;
    As[0][fk + 3][fm] = av.w;
    *(float4*)&Bs[0][gk][gn] = bv;
    __syncthreads();

    for (int kc = 0; kc < 16; ++kc) {
        const int s = kc & 1;
        if (kc < 15) {
            const int k0 = (kc + 1) * 16;
            av = *(const float4*)&X[(m0 + fm) * 256 + k0 + fk];
            bv = *(const float4*)&W[(k0 + gk) * 256 + n0 + gn];
        }

        #pragma unroll
        for (int kk = 0; kk < 16; ++kk) {
            float4 a = *(const float4*)&As[s][kk][ty * 4];
            float4 b = *(const float4*)&Bs[s][kk][tx * 4];
            float avr[4] = {a.x, a.y, a.z, a.w};
            float bvr[4] = {b.x, b.y, b.z, b.w};
            #pragma unroll
            for (int i = 0; i < 4; ++i)
                #pragma unroll
                for (int j = 0; j < 4; ++j)
                    acc[i][j] = fmaf(avr[i], bvr[j], acc[i][j]);
        }

        if (kc < 15) {
            const int s2 = s ^ 1;
            As[s2][fk + 0][fm] = av.x;
            As[s2][fk + 1][fm] = av.y;
            As[s2][fk + 2][fm] = av.z;
            As[s2][fk + 3][fm] = av.w;
            *(float4*)&Bs[s2][gk][gn] = bv;
            __syncthreads();
        }
    }

    #pragma unroll
    for (int i = 0; i < 4; ++i) {
        int m = m0 + ty * 4 + i;
        int n = n0 + tx * 4;
        float c0 = acc[i][0], c1 = acc[i][1], c2 = acc[i][2], c3 = acc[i][3];
        if (sel) {
            c0 += b1[n + 0]; c1 += b1[n + 1];
            c2 += b1[n + 2]; c3 += b1[n + 3];
        }
        float4 o = {c0, c1, c2, c3};
        *(float4*)&out[m * 256 + n] = o;
    }

    // PDL: allow the dependent cross launch to begin scheduling its blocks.
    // (Scheduling hint only; the secondary's cudaGridDependencySynchronize
    // still waits for full grid completion + memory visibility.)
    cudaTriggerProgrammaticLaunchCompletion();
}

// ---------------------------------------------------------------------------
// Cross kernel (R10 form + PDL prologue): block = (b, 32n x 32m) tile;
// thread = 2x2 micro-tile as two f32x2 groups. d chunked 4x64, double-
// buffered smem + register prefetch, one sync per chunk.
// ws2 fill + const setup run BEFORE the grid dependency sync (they consume
// only kernel inputs, not GEMM output), hiding them under the GEMM tail.
// ---------------------------------------------------------------------------
#define SX 34
#define DCH 64

__global__ __launch_bounds__(256, 4) void cross_kernel(
    const float* __restrict__ W2,
    const float* __restrict__ b2,
    float* __restrict__ out)
{
    extern __shared__ float sm[];
    float* xs0 = sm;                     // [2][DCH*SX]
    float* ys0 = sm + 2 * DCH * SX;      // [2][DCH*SX]
    float* ws2 = sm + 4 * DCH * SX;      // [512]

    const int tx = threadIdx.x;        // 0..15 -> m
    const int ty = threadIdx.y;        // 0..15 -> n
    const int t  = ty * 16 + tx;
    const int bz = blockIdx.z;
    const int n0 = blockIdx.y * 32;
    const int m0 = blockIdx.x * 32;

    const float* xp = g_xp  + (bz * NN + n0) * DD;
    const float* yp = g_ypb + (bz * NN + m0) * DD;

    // --- pre-dependency phase: inputs only (W2, b2), no GEMM output ---
    {
        float wv = 0.5f * W2[t];
        u64 wp; PK(wp, wv, wv);
        *(u64*)&ws2[2 * t] = wp;
    }
    const float bb = b2[0];

    u64 C0P, C1P;
    PK(C0P, GC0, GC0);
    PK(C1P, GC1, GC1);

    // --- wait for the GEMM grid (full completion + visibility) ---
    cudaGridDependencySynchronize();

    u64 acc0 = 0ull, acc1 = 0ull;   // (a00,a01), (a10,a11)

    const int r  = t >> 3;    // 0..31
    const int cq = t & 7;     // 0..7

    float4 px[2], py[2];

    // prologue: LDG chunk 0, STS to buffer 0
    #pragma unroll
    for (int it = 0; it < 2; ++it) {
        int dg = 32 * it + 4 * cq;
        px[it] = *(const float4*)&xp[r * 256 + dg];
        py[it] = *(const float4*)&yp[r * 256 + dg];
    }
    #pragma unroll
    for (int it = 0; it < 2; ++it) {
        int dl = 32 * it + 4 * cq;
        xs0[(dl + 0) * SX + r] = px[it].x;
        xs0[(dl + 1) * SX + r] = px[it].y;
        xs0[(dl + 2) * SX + r] = px[it].z;
        xs0[(dl + 3) * SX + r] = px[it].w;
        ys0[(dl + 0) * SX + r] = py[it].x;
        ys0[(dl + 1) * SX + r] = py[it].y;
        ys0[(dl + 2) * SX + r] = py[it].z;
        ys0[(dl + 3) * SX + r] = py[it].w;
    }
    __syncthreads();

    #pragma unroll
    for (int c = 0; c < 4; ++c) {
        const int buf = c & 1;
        const float* xsb = xs0 + buf * DCH * SX;
        const float* ysb = ys0 + buf * DCH * SX;
        const float* xsp = xsb + 2 * ty;
        const float* ysp = ysb + 2 * tx;
        const float* wc  = ws2 + c * 2 * DCH;

        if (c < 3) {
            #pragma unroll
            for (int it = 0; it < 2; ++it) {
                int dg = (c + 1) * DCH + 32 * it + 4 * cq;
                px[it] = *(const float4*)&xp[r * 256 + dg];
                py[it] = *(const float4*)&yp[r * 256 + dg];
            }
        }

        #pragma unroll 8
        for (int d = 0; d < DCH; ++d) {
            float2 xv = *(const float2*)&xsp[d * SX];
            u64 Y = *(const u64*)&ysp[d * SX];
            u64 W = *(const u64*)&wc[2 * d];
            u64 X0, X1;
            PK(X0, xv.x, xv.x);
            PK(X1, xv.y, xv.y);

            #define GEL2(ACC, XB)                               \
            {                                                   \
                u64 H, Q, S, U, T, G;                           \
                float u0, u1, t0, t1;                           \
                F2ADD(H, XB, Y);                                \
                F2MUL(Q, H, H);                                 \
                F2FMA(S, Q, C1P, C0P);                          \
                F2MUL(U, H, S);                                 \
                UNPK(u0, u1, U);                                \
                t0 = tanh_fast(u0);                             \
                t1 = tanh_fast(u1);                             \
                PK(T, t0, t1);                                  \
                F2FMA(G, H, T, H);                              \
                F2FMA(ACC, G, W, ACC);                          \
            }

            GEL2(acc0, X0)
            GEL2(acc1, X1)
            #undef GEL2
        }

        if (c < 3) {
            float* xsn = xs0 + (buf ^ 1) * DCH * SX;
            float* ysn = ys0 + (buf ^ 1) * DCH * SX;
            #pragma unroll
            for (int it = 0; it < 2; ++it) {
                int dl = 32 * it + 4 * cq;
                xsn[(dl + 0) * SX + r] = px[it].x;
                xsn[(dl + 1) * SX + r] = px[it].y;
                xsn[(dl + 2) * SX + r] = px[it].z;
                xsn[(dl + 3) * SX + r] = px[it].w;
                ysn[(dl + 0) * SX + r] = py[it].x;
                ysn[(dl + 1) * SX + r] = py[it].y;
                ysn[(dl + 2) * SX + r] = py[it].z;
                ysn[(dl + 3) * SX + r] = py[it].w;
            }
            __syncthreads();
        }
    }

    u64 bpair; PK(bpair, bb, bb);
    F2ADD(acc0, acc0, bpair);
    F2ADD(acc1, acc1, bpair);

    const int n = n0 + 2 * ty;
    const int m = m0 + 2 * tx;
    float* orow = out + (size_t)(bz * NN + n) * NN + m;
    *(u64*)&orow[0]  = acc0;
    *(u64*)&orow[NN] = acc1;
}

// ---------------------------------------------------------------------------
extern "C" void kernel_launch(void* const* d_in, const int* in_sizes, int n_in,
                              void* d_out, int out_size)
{
    const float* x  = (const float*)d_in[0];
    const float* y  = (const float*)d_in[1];
    const float* W1 = (const float*)d_in[2];
    const float* b1 = (const float*)d_in[3];
    const float* W2 = (const float*)d_in[4];
    const float* b2 = (const float*)d_in[5];
    float* out = (float*)d_out;

    (void)in_sizes; (void)n_in; (void)out_size;

    const int smem_cross = (4 * DCH * SX + 512) * (int)sizeof(float);
    cudaFuncSetAttribute(cross_kernel,
                         cudaFuncAttributeMaxDynamicSharedMemorySize,
                         smem_cross);

    dim3 gblk(16, 16);      // 256 threads
    dim3 ggrid(4, 32, 2);   // 256 blocks, both GEMMs in one launch
    gemm_kernel<<<ggrid, gblk>>>(x, y, W1, b1);

    // Cross launched with PDL: blocks become resident and run their
    // pre-dependency phase while the GEMM drains.
    dim3 cblk(16, 16);
    dim3 cgrid(16, 16, 4);  // (m-tiles, n-tiles, batch)

    cudaLaunchConfig_t cfg = {};
    cfg.gridDim = cgrid;
    cfg.blockDim = cblk;
    cfg.dynamicSmemBytes = (size_t)smem_cross;
    cfg.stream = 0;
    cudaLaunchAttribute attrs[1];
    attrs[0].id = cudaLaunchAttributeProgrammaticStreamSerialization;
    attrs[0].val.programmaticStreamSerializationAllowed = 1;
    cfg.attrs = attrs;
    cfg.numAttrs = 1;
    cudaLaunchKernelEx(&cfg, cross_kernel, W2, b2, out);
}